// round 13
// baseline (speedup 1.0000x reference)
#include <cuda_runtime.h>
#include <cuda_bf16.h>
#include <cstdint>

static constexpr int Bn = 128;
static constexpr int Sn = 1024;
static constexpr int Dn = 1024;
static constexpr float LOG2F_ = 0.69314718055994530942f;

__device__ double g_pos_acc;
__device__ double g_neg_acc;
__device__ int g_lens[Bn];
__device__ int g_ticket;
__device__ __nv_bfloat16 g_ctx_bf16[Bn * Dn];

// dynamic smem (1024-aligned window):
// A0[8K] | A1[8K] | B0[16K] | B1[16K]  (A: 64 rows x 128B, B: 128 rows x 128B)
__host__ __device__ constexpr uint32_t OFF_A(int buf) { return buf ? 8192u : 0u; }
__host__ __device__ constexpr uint32_t OFF_B(int buf) { return buf ? 32768u : 16384u; }

// ---------------------------------------------------------------------------
// prep: ctx fp32 -> bf16 (1 float4/thread), lens via int4 + shfl reduction,
// zero global accumulators + ticket (graph-replay safe).
// ---------------------------------------------------------------------------
__global__ void __launch_bounds__(256) prep_kernel(const float* __restrict__ ctx,
                                                   const int* __restrict__ mask) {
    const int b = blockIdx.x;
    const int tid = threadIdx.x;
    float4 v = reinterpret_cast<const float4*>(ctx + b * Dn)[tid];
    __nv_bfloat162 h0 = __float22bfloat162_rn(make_float2(v.x, v.y));
    __nv_bfloat162 h1 = __float22bfloat162_rn(make_float2(v.z, v.w));
    uint2 packed;
    packed.x = *reinterpret_cast<uint32_t*>(&h0);
    packed.y = *reinterpret_cast<uint32_t*>(&h1);
    reinterpret_cast<uint2*>(g_ctx_bf16 + b * Dn)[tid] = packed;
    int4 m = reinterpret_cast<const int4*>(mask + b * Sn)[tid];
    int s = m.x + m.y + m.z + m.w;
    #pragma unroll
    for (int off = 16; off > 0; off >>= 1)
        s += __shfl_xor_sync(0xffffffffu, s, off);
    __shared__ int wsum[8];
    if ((tid & 31) == 0) wsum[tid >> 5] = s;
    __syncthreads();
    if (tid == 0) {
        int tot = 0;
        #pragma unroll
        for (int i = 0; i < 8; i++) tot += wsum[i];
        g_lens[b] = tot > 0 ? tot : 1;
        if (b == 0) { g_pos_acc = 0.0; g_neg_acc = 0.0; g_ticket = 0; }
    }
}

__device__ __forceinline__ void ldm_x4(uint32_t& r0, uint32_t& r1, uint32_t& r2,
                                       uint32_t& r3, uint32_t addr) {
    asm volatile("ldmatrix.sync.aligned.m8n8.x4.shared.b16 {%0,%1,%2,%3}, [%4];"
                 : "=r"(r0), "=r"(r1), "=r"(r2), "=r"(r3) : "r"(addr));
}

__device__ __forceinline__ void mma_bf16(float* c, const uint32_t* a, const uint32_t* b) {
    asm volatile("mma.sync.aligned.m16n8k16.row.col.f32.bf16.bf16.f32 "
                 "{%0,%1,%2,%3}, {%4,%5,%6,%7}, {%8,%9}, {%0,%1,%2,%3};"
                 : "+f"(c[0]), "+f"(c[1]), "+f"(c[2]), "+f"(c[3])
                 : "r"(a[0]), "r"(a[1]), "r"(a[2]), "r"(a[3]), "r"(b[0]), "r"(b[1]));
}

#define CP_ASYNC16(dst, src) \
    asm volatile("cp.async.cg.shared.global [%0], [%1], 16;" :: "r"(dst), "l"(src))
#define CP_COMMIT() asm volatile("cp.async.commit_group;")
#define CP_WAIT0()  asm volatile("cp.async.wait_group 0;" ::: "memory")

// ---------------------------------------------------------------------------
// main: BM=64 (one b), BN=128, BK=64, 4 warps (2x2 of 32x64), 3 CTAs/SM.
// Fragment-level software pipeline: ldmatrix for ks+1 issued before mma(ks)
// using double fragment buffers (cur/nxt) -> per-warp L1/tensor overlap.
// Alive-first grid remap (s-major), EARLY EXIT + dead fast path.
// ---------------------------------------------------------------------------
__global__ void __launch_bounds__(128, 3)
mi_main_kernel(const float* __restrict__ seq, float* __restrict__ out) {
    extern __shared__ __align__(16) uint8_t dynsm_raw[];
    __shared__ float redp[4], redn[4];

    const int tid = threadIdx.x;
    const int lane = tid & 31;
    const int w = tid >> 5;        // 0..3
    const int wm = w >> 1;         // warp row (2 x 32 rows)
    const int wn = w & 1;          // warp col (2 x 64 cols)
    // s-major remap: alive tiles cluster at low blockIdx
    const int s_tile = blockIdx.x >> 7;
    const int b = blockIdx.x & (Bn - 1);
    const int s0 = s_tile * 64;
    const int tok0 = b * Sn + s0;
    const int len = g_lens[b];

    if (s0 >= len) {               // ---- dead tile: straight to ticket ----
        if (tid == 0) {
            __threadfence();
            int old = atomicAdd(&g_ticket, 1);
            if (old == (int)gridDim.x - 1) {
                double nn = 0.0;
                for (int i = 0; i < Bn; i++) nn += (double)g_lens[i];
                double pp = atomicAdd(&g_pos_acc, 0.0);
                double qq = atomicAdd(&g_neg_acc, 0.0);
                out[0] = (float)(qq / (nn * (double)(Bn - 1)) - pp / nn);
            }
        }
        return;
    }

    const uint32_t rawB = (uint32_t)__cvta_generic_to_shared(dynsm_raw);
    const uint32_t sBase = (rawB + 1023u) & ~1023u;
    uint8_t* dynsm = dynsm_raw + (sBase - rawB);

    float acc[2][8][4];
    #pragma unroll
    for (int i = 0; i < 2; i++)
        #pragma unroll
        for (int j = 0; j < 8; j++)
            #pragma unroll
            for (int r = 0; r < 4; r++) acc[i][j][r] = 0.0f;

    float4 pa[4];   // A half-tile staging: 32 rows x 64 k fp32 / 128 thr

    auto loadA_half = [&](int kb, int h) {
        #pragma unroll
        for (int j = 0; j < 4; j++) {
            int fi = tid + j * 128;
            int rw = h * 32 + (fi >> 4);
            int fc = fi & 15;
            pa[j] = *reinterpret_cast<const float4*>(
                seq + (size_t)(tok0 + rw) * Dn + kb * 64 + fc * 4);
        }
    };
    auto storeA_half = [&](int buf, int h) {
        #pragma unroll
        for (int j = 0; j < 4; j++) {
            int fi = tid + j * 128;
            int rw = h * 32 + (fi >> 4);
            int fc = fi & 15;
            __nv_bfloat162 h0 = __float22bfloat162_rn(make_float2(pa[j].x, pa[j].y));
            __nv_bfloat162 h1 = __float22bfloat162_rn(make_float2(pa[j].z, pa[j].w));
            uint2 vv;
            vv.x = *reinterpret_cast<uint32_t*>(&h0);
            vv.y = *reinterpret_cast<uint32_t*>(&h1);
            uint32_t off = rw * 128 + fc * 8;
            uint32_t sw = off ^ ((off >> 3) & 0x70);
            *reinterpret_cast<uint2*>(dynsm + OFF_A(buf) + sw) = vv;
        }
    };
    auto loadB = [&](int kb, int buf) {
        #pragma unroll
        for (int j = 0; j < 8; j++) {
            int lc = tid + j * 128;
            int rw = lc >> 3;
            int cc = lc & 7;
            uint32_t off = rw * 128 + cc * 16;
            uint32_t sw = off ^ ((off >> 3) & 0x70);
            CP_ASYNC16(sBase + OFF_B(buf) + sw,
                       g_ctx_bf16 + rw * Dn + kb * 64 + cc * 8);
        }
    };

    // fragment double-buffers for the ks pipeline
    uint32_t afr[2][2][4];
    uint32_t bfr[2][8][2];

    auto load_frags = [&](int sl, int buf, int ks) {
        const uint32_t aB = sBase + OFF_A(buf);
        const uint32_t bB = sBase + OFF_B(buf);
        #pragma unroll
        for (int mf = 0; mf < 2; mf++) {
            int r = wm * 32 + mf * 16 + (lane & 15);
            int ch = ks * 2 + (lane >> 4);
            ldm_x4(afr[sl][mf][0], afr[sl][mf][1], afr[sl][mf][2], afr[sl][mf][3],
                   aB + r * 128 + ((ch ^ (r & 7)) << 4));
        }
        #pragma unroll
        for (int nq = 0; nq < 4; nq++) {
            int r = wn * 64 + nq * 16 + (lane & 7) + ((lane & 16) >> 1);
            int ch = ks * 2 + ((lane >> 3) & 1);
            uint32_t t0, t1, t2, t3;
            ldm_x4(t0, t1, t2, t3, bB + r * 128 + ((ch ^ (r & 7)) << 4));
            bfr[sl][nq * 2][0] = t0; bfr[sl][nq * 2][1] = t1;
            bfr[sl][nq * 2 + 1][0] = t2; bfr[sl][nq * 2 + 1][1] = t3;
        }
    };
    auto do_mma = [&](int sl) {
        #pragma unroll
        for (int mf = 0; mf < 2; mf++)
            #pragma unroll
            for (int nf = 0; nf < 8; nf++)
                mma_bf16(acc[mf][nf], afr[sl][mf], bfr[sl][nf]);
    };

    // prologue: fill buffer 0
    loadA_half(0, 0); storeA_half(0, 0);
    loadA_half(0, 1); storeA_half(0, 1);
    loadB(0, 0); CP_COMMIT();
    CP_WAIT0();
    __syncthreads();

    for (int kb = 0; kb < 16; kb++) {
        const int cur = kb & 1;
        const int nxt = cur ^ 1;
        if (kb < 15) {
            loadB(kb + 1, nxt);
            CP_COMMIT();
            loadA_half(kb + 1, 0);
        }
        // pipelined ks loop: ldm(ks+1) issued before mma(ks)
        load_frags(0, cur, 0);
        #pragma unroll
        for (int ks = 0; ks < 4; ks++) {
            const int sl = ks & 1;
            if (ks < 3) load_frags(sl ^ 1, cur, ks + 1);
            if (ks == 1 && kb < 15) { storeA_half(nxt, 0); loadA_half(kb + 1, 1); }
            do_mma(sl);
        }
        if (kb < 15) {
            storeA_half(nxt, 1);
            CP_WAIT0();
        }
        __syncthreads();
    }

    // JSD epilogue: masked by (s < len), diag/off-diag split
    float pos = 0.0f, neg = 0.0f;
    #pragma unroll
    for (int mf = 0; mf < 2; mf++) {
        #pragma unroll
        for (int nf = 0; nf < 8; nf++) {
            #pragma unroll
            for (int r = 0; r < 4; r++) {
                int row = wm * 32 + mf * 16 + (lane >> 2) + ((r & 2) ? 8 : 0);
                int s   = s0 + row;
                int k   = wn * 64 + nf * 8 + ((lane & 3) << 1) + (r & 1);
                float v = acc[mf][nf][r];
                if (s < len) {
                    float sp = fmaxf(-v, 0.0f) + __logf(1.0f + __expf(-fabsf(v)));
                    if (k == b) pos += LOG2F_ - sp;
                    else        neg += sp + v - LOG2F_;
                }
            }
        }
    }
    #pragma unroll
    for (int off = 16; off > 0; off >>= 1) {
        pos += __shfl_xor_sync(0xffffffffu, pos, off);
        neg += __shfl_xor_sync(0xffffffffu, neg, off);
    }
    if (lane == 0) { redp[w] = pos; redn[w] = neg; }
    __syncthreads();
    if (tid == 0) {
        double p = (double)redp[0] + redp[1] + redp[2] + redp[3];
        double n = (double)redn[0] + redn[1] + redn[2] + redn[3];
        atomicAdd(&g_pos_acc, p);
        atomicAdd(&g_neg_acc, n);
        __threadfence();
        int old = atomicAdd(&g_ticket, 1);
        if (old == (int)gridDim.x - 1) {   // last CTA finalizes
            double nn = 0.0;
            for (int i = 0; i < Bn; i++) nn += (double)g_lens[i];
            double pp = atomicAdd(&g_pos_acc, 0.0);
            double qq = atomicAdd(&g_neg_acc, 0.0);
            out[0] = (float)(qq / (nn * (double)(Bn - 1)) - pp / nn);
        }
    }
}

extern "C" void kernel_launch(void* const* d_in, const int* in_sizes, int n_in,
                              void* d_out, int out_size) {
    const float* seq  = (const float*)d_in[0];
    const float* ctx  = (const float*)d_in[1];
    const int*   mask = (const int*)d_in[2];
    static bool attr_set = false;
    if (!attr_set) {
        cudaFuncSetAttribute(mi_main_kernel,
                             cudaFuncAttributeMaxDynamicSharedMemorySize, 50176);
        attr_set = true;
    }
    prep_kernel<<<Bn, 256>>>(ctx, mask);
    mi_main_kernel<<<(Bn * Sn) / 64, 128, 50176>>>(seq, (float*)d_out);
}

// round 14
// speedup vs baseline: 1.1585x; 1.1585x over previous
#include <cuda_runtime.h>
#include <cuda_bf16.h>
#include <cstdint>

static constexpr int Bn = 128;
static constexpr int Sn = 1024;
static constexpr int Dn = 1024;
static constexpr int NTILES = (Bn * Sn) / 64;      // 2048, s-major
static constexpr int NCTA = 592;                   // 148 SMs x 4 CTAs
static constexpr float LOG2F_ = 0.69314718055994530942f;

__device__ double g_pos_acc;
__device__ double g_neg_acc;
__device__ int g_lens[Bn];
__device__ int g_ticket;
__device__ int g_fetch;
__device__ __nv_bfloat16 g_ctx_bf16[Bn * Dn];

// dynamic smem (1024-aligned window):
// A0[8K] | A1[8K] | B0[16K] | B1[16K]
__host__ __device__ constexpr uint32_t OFF_A(int buf) { return buf ? 8192u : 0u; }
__host__ __device__ constexpr uint32_t OFF_B(int buf) { return buf ? 32768u : 16384u; }

// ---------------------------------------------------------------------------
// prep: ctx fp32 -> bf16, lens, zero accumulators + ticket + fetch counter
// ---------------------------------------------------------------------------
__global__ void __launch_bounds__(256) prep_kernel(const float* __restrict__ ctx,
                                                   const int* __restrict__ mask) {
    const int b = blockIdx.x;
    const int tid = threadIdx.x;
    float4 v = reinterpret_cast<const float4*>(ctx + b * Dn)[tid];
    __nv_bfloat162 h0 = __float22bfloat162_rn(make_float2(v.x, v.y));
    __nv_bfloat162 h1 = __float22bfloat162_rn(make_float2(v.z, v.w));
    uint2 packed;
    packed.x = *reinterpret_cast<uint32_t*>(&h0);
    packed.y = *reinterpret_cast<uint32_t*>(&h1);
    reinterpret_cast<uint2*>(g_ctx_bf16 + b * Dn)[tid] = packed;
    int4 m = reinterpret_cast<const int4*>(mask + b * Sn)[tid];
    int s = m.x + m.y + m.z + m.w;
    #pragma unroll
    for (int off = 16; off > 0; off >>= 1)
        s += __shfl_xor_sync(0xffffffffu, s, off);
    __shared__ int wsum[8];
    if ((tid & 31) == 0) wsum[tid >> 5] = s;
    __syncthreads();
    if (tid == 0) {
        int tot = 0;
        #pragma unroll
        for (int i = 0; i < 8; i++) tot += wsum[i];
        g_lens[b] = tot > 0 ? tot : 1;
        if (b == 0) { g_pos_acc = 0.0; g_neg_acc = 0.0; g_ticket = 0; g_fetch = 0; }
    }
}

__device__ __forceinline__ void ldm_x4(uint32_t& r0, uint32_t& r1, uint32_t& r2,
                                       uint32_t& r3, uint32_t addr) {
    asm volatile("ldmatrix.sync.aligned.m8n8.x4.shared.b16 {%0,%1,%2,%3}, [%4];"
                 : "=r"(r0), "=r"(r1), "=r"(r2), "=r"(r3) : "r"(addr));
}

__device__ __forceinline__ void mma_bf16(float* c, const uint32_t* a, const uint32_t* b) {
    asm volatile("mma.sync.aligned.m16n8k16.row.col.f32.bf16.bf16.f32 "
                 "{%0,%1,%2,%3}, {%4,%5,%6,%7}, {%8,%9}, {%0,%1,%2,%3};"
                 : "+f"(c[0]), "+f"(c[1]), "+f"(c[2]), "+f"(c[3])
                 : "r"(a[0]), "r"(a[1]), "r"(a[2]), "r"(a[3]), "r"(b[0]), "r"(b[1]));
}

#define CP_ASYNC16(dst, src) \
    asm volatile("cp.async.cg.shared.global [%0], [%1], 16;" :: "r"(dst), "l"(src))
#define CP_COMMIT() asm volatile("cp.async.commit_group;")
#define CP_WAIT0()  asm volatile("cp.async.wait_group 0;" ::: "memory")

// ---------------------------------------------------------------------------
// main: PERSISTENT work-stealing over s-major tiles (kills wave quantization).
// Inner loop per tile is byte-identical to the 93.7us R12 kernel:
// BM=64, BN=128, BK=64, 4 warps (2x2 of 32x64), pa[4] half-stage A prefetch.
// pos/neg accumulate across tiles; one reduction + ticket per CTA.
// ---------------------------------------------------------------------------
__global__ void __launch_bounds__(128, 4)
mi_main_kernel(const float* __restrict__ seq, float* __restrict__ out) {
    extern __shared__ __align__(16) uint8_t dynsm_raw[];
    __shared__ float redp[4], redn[4];
    __shared__ int sh_t;

    const int tid = threadIdx.x;
    const int lane = tid & 31;
    const int w = tid >> 5;        // 0..3
    const int wm = w >> 1;         // warp row (2 x 32 rows)
    const int wn = w & 1;          // warp col (2 x 64 cols)

    const uint32_t rawB = (uint32_t)__cvta_generic_to_shared(dynsm_raw);
    const uint32_t sBase = (rawB + 1023u) & ~1023u;
    uint8_t* dynsm = dynsm_raw + (sBase - rawB);

    float pos = 0.0f, neg = 0.0f;

    while (true) {
        __syncthreads();                       // protect sh_t reuse
        if (tid == 0) sh_t = atomicAdd(&g_fetch, 1);
        __syncthreads();
        const int t = sh_t;
        if (t >= NTILES) break;

        // s-major: alive tiles cluster at low t
        const int s0 = (t >> 7) * 64;
        const int b = t & (Bn - 1);
        const int len = g_lens[b];
        if (s0 >= len) continue;               // dead tile: cheap skip
        const int tok0 = b * Sn + s0;

        float acc[2][8][4];
        #pragma unroll
        for (int i = 0; i < 2; i++)
            #pragma unroll
            for (int j = 0; j < 8; j++)
                #pragma unroll
                for (int r = 0; r < 4; r++) acc[i][j][r] = 0.0f;

        float4 pa[4];   // A half-tile staging: 32 rows x 64 k fp32 / 128 thr

        auto loadA_half = [&](int kb, int h) {
            #pragma unroll
            for (int j = 0; j < 4; j++) {
                int fi = tid + j * 128;
                int rw = h * 32 + (fi >> 4);
                int fc = fi & 15;
                pa[j] = *reinterpret_cast<const float4*>(
                    seq + (size_t)(tok0 + rw) * Dn + kb * 64 + fc * 4);
            }
        };
        auto storeA_half = [&](int buf, int h) {
            #pragma unroll
            for (int j = 0; j < 4; j++) {
                int fi = tid + j * 128;
                int rw = h * 32 + (fi >> 4);
                int fc = fi & 15;
                __nv_bfloat162 h0 = __float22bfloat162_rn(make_float2(pa[j].x, pa[j].y));
                __nv_bfloat162 h1 = __float22bfloat162_rn(make_float2(pa[j].z, pa[j].w));
                uint2 vv;
                vv.x = *reinterpret_cast<uint32_t*>(&h0);
                vv.y = *reinterpret_cast<uint32_t*>(&h1);
                uint32_t off = rw * 128 + fc * 8;
                uint32_t sw = off ^ ((off >> 3) & 0x70);
                *reinterpret_cast<uint2*>(dynsm + OFF_A(buf) + sw) = vv;
            }
        };
        auto loadB = [&](int kb, int buf) {
            #pragma unroll
            for (int j = 0; j < 8; j++) {
                int lc = tid + j * 128;
                int rw = lc >> 3;
                int cc = lc & 7;
                uint32_t off = rw * 128 + cc * 16;
                uint32_t sw = off ^ ((off >> 3) & 0x70);
                CP_ASYNC16(sBase + OFF_B(buf) + sw,
                           g_ctx_bf16 + rw * Dn + kb * 64 + cc * 8);
            }
        };
        auto compute_ks = [&](int buf, int ks) {
            const uint32_t aB = sBase + OFF_A(buf);
            const uint32_t bB = sBase + OFF_B(buf);
            uint32_t afr[2][4];
            #pragma unroll
            for (int mf = 0; mf < 2; mf++) {
                int r = wm * 32 + mf * 16 + (lane & 15);
                int ch = ks * 2 + (lane >> 4);
                ldm_x4(afr[mf][0], afr[mf][1], afr[mf][2], afr[mf][3],
                       aB + r * 128 + ((ch ^ (r & 7)) << 4));
            }
            uint32_t bfr[8][2];
            #pragma unroll
            for (int nq = 0; nq < 4; nq++) {
                int r = wn * 64 + nq * 16 + (lane & 7) + ((lane & 16) >> 1);
                int ch = ks * 2 + ((lane >> 3) & 1);
                uint32_t t0, t1, t2, t3;
                ldm_x4(t0, t1, t2, t3, bB + r * 128 + ((ch ^ (r & 7)) << 4));
                bfr[nq * 2][0] = t0; bfr[nq * 2][1] = t1;
                bfr[nq * 2 + 1][0] = t2; bfr[nq * 2 + 1][1] = t3;
            }
            #pragma unroll
            for (int mf = 0; mf < 2; mf++)
                #pragma unroll
                for (int nf = 0; nf < 8; nf++)
                    mma_bf16(acc[mf][nf], afr[mf], bfr[nf]);
        };

        // prologue: fill buffer 0
        loadA_half(0, 0); storeA_half(0, 0);
        loadA_half(0, 1); storeA_half(0, 1);
        loadB(0, 0); CP_COMMIT();
        CP_WAIT0();
        __syncthreads();

        for (int kb = 0; kb < 16; kb++) {
            const int cur = kb & 1;
            const int nxt = cur ^ 1;
            if (kb < 15) {
                loadB(kb + 1, nxt);
                CP_COMMIT();
                loadA_half(kb + 1, 0);
            }
            compute_ks(cur, 0);
            compute_ks(cur, 1);
            if (kb < 15) {
                storeA_half(nxt, 0);
                loadA_half(kb + 1, 1);
            }
            compute_ks(cur, 2);
            compute_ks(cur, 3);
            if (kb < 15) {
                storeA_half(nxt, 1);
                CP_WAIT0();
            }
            __syncthreads();
        }

        // JSD epilogue: masked by (s < len), diag/off-diag split
        #pragma unroll
        for (int mf = 0; mf < 2; mf++) {
            #pragma unroll
            for (int nf = 0; nf < 8; nf++) {
                #pragma unroll
                for (int r = 0; r < 4; r++) {
                    int row = wm * 32 + mf * 16 + (lane >> 2) + ((r & 2) ? 8 : 0);
                    int s   = s0 + row;
                    int k   = wn * 64 + nf * 8 + ((lane & 3) << 1) + (r & 1);
                    float v = acc[mf][nf][r];
                    if (s < len) {
                        float sp = fmaxf(-v, 0.0f) + __logf(1.0f + __expf(-fabsf(v)));
                        if (k == b) pos += LOG2F_ - sp;
                        else        neg += sp + v - LOG2F_;
                    }
                }
            }
        }
    }

    // ---- once per CTA: reduction + ticket ----
    #pragma unroll
    for (int off = 16; off > 0; off >>= 1) {
        pos += __shfl_xor_sync(0xffffffffu, pos, off);
        neg += __shfl_xor_sync(0xffffffffu, neg, off);
    }
    if (lane == 0) { redp[w] = pos; redn[w] = neg; }
    __syncthreads();
    if (tid == 0) {
        double p = (double)redp[0] + redp[1] + redp[2] + redp[3];
        double n = (double)redn[0] + redn[1] + redn[2] + redn[3];
        if (p != 0.0 || n != 0.0) {
            atomicAdd(&g_pos_acc, p);
            atomicAdd(&g_neg_acc, n);
        }
        __threadfence();
        int old = atomicAdd(&g_ticket, 1);
        if (old == (int)gridDim.x - 1) {   // last CTA finalizes
            double nn = 0.0;
            for (int i = 0; i < Bn; i++) nn += (double)g_lens[i];
            double pp = atomicAdd(&g_pos_acc, 0.0);
            double qq = atomicAdd(&g_neg_acc, 0.0);
            out[0] = (float)(qq / (nn * (double)(Bn - 1)) - pp / nn);
        }
    }
}

extern "C" void kernel_launch(void* const* d_in, const int* in_sizes, int n_in,
                              void* d_out, int out_size) {
    const float* seq  = (const float*)d_in[0];
    const float* ctx  = (const float*)d_in[1];
    const int*   mask = (const int*)d_in[2];
    static bool attr_set = false;
    if (!attr_set) {
        cudaFuncSetAttribute(mi_main_kernel,
                             cudaFuncAttributeMaxDynamicSharedMemorySize, 50176);
        attr_set = true;
    }
    prep_kernel<<<Bn, 256>>>(ctx, mask);
    mi_main_kernel<<<NCTA, 128, 50176>>>(seq, (float*)d_out);
}

// round 15
// speedup vs baseline: 1.1823x; 1.0205x over previous
#include <cuda_runtime.h>
#include <cuda_bf16.h>
#include <cstdint>

static constexpr int Bn = 128;
static constexpr int Sn = 1024;
static constexpr int Dn = 1024;
static constexpr int NTILES = (Bn * Sn) / 128;     // 1024 tiles, s-major
static constexpr int NCTA = 296;                   // 148 SMs x 2 CTAs
static constexpr float LOG2F_ = 0.69314718055994530942f;

__device__ double g_pos_acc;
__device__ double g_neg_acc;
__device__ int g_lens[Bn];
__device__ int g_ticket;
__device__ int g_fetch;
__device__ __nv_bfloat16 g_ctx_bf16[Bn * Dn];

// dynamic smem (1024-aligned window):
// A0[16K] | A1[16K] | B0[16K] | B1[16K]   (all 128 rows x 128B, SW)
__host__ __device__ constexpr uint32_t OFF_A(int buf) { return (uint32_t)buf * 16384u; }
__host__ __device__ constexpr uint32_t OFF_B(int buf) { return 32768u + (uint32_t)buf * 16384u; }
static constexpr uint32_t SMEM_BYTES = 65536u + 1024u;

// ---------------------------------------------------------------------------
// prep: ctx fp32 -> bf16, lens, zero accumulators + ticket + fetch counter
// ---------------------------------------------------------------------------
__global__ void __launch_bounds__(256) prep_kernel(const float* __restrict__ ctx,
                                                   const int* __restrict__ mask) {
    const int b = blockIdx.x;
    const int tid = threadIdx.x;
    float4 v = reinterpret_cast<const float4*>(ctx + b * Dn)[tid];
    __nv_bfloat162 h0 = __float22bfloat162_rn(make_float2(v.x, v.y));
    __nv_bfloat162 h1 = __float22bfloat162_rn(make_float2(v.z, v.w));
    uint2 packed;
    packed.x = *reinterpret_cast<uint32_t*>(&h0);
    packed.y = *reinterpret_cast<uint32_t*>(&h1);
    reinterpret_cast<uint2*>(g_ctx_bf16 + b * Dn)[tid] = packed;
    int4 m = reinterpret_cast<const int4*>(mask + b * Sn)[tid];
    int s = m.x + m.y + m.z + m.w;
    #pragma unroll
    for (int off = 16; off > 0; off >>= 1)
        s += __shfl_xor_sync(0xffffffffu, s, off);
    __shared__ int wsum[8];
    if ((tid & 31) == 0) wsum[tid >> 5] = s;
    __syncthreads();
    if (tid == 0) {
        int tot = 0;
        #pragma unroll
        for (int i = 0; i < 8; i++) tot += wsum[i];
        g_lens[b] = tot > 0 ? tot : 1;
        if (b == 0) { g_pos_acc = 0.0; g_neg_acc = 0.0; g_ticket = 0; g_fetch = 0; }
    }
}

__device__ __forceinline__ void ldm_x4(uint32_t& r0, uint32_t& r1, uint32_t& r2,
                                       uint32_t& r3, uint32_t addr) {
    asm volatile("ldmatrix.sync.aligned.m8n8.x4.shared.b16 {%0,%1,%2,%3}, [%4];"
                 : "=r"(r0), "=r"(r1), "=r"(r2), "=r"(r3) : "r"(addr));
}

__device__ __forceinline__ void mma_bf16(float* c, const uint32_t* a, const uint32_t* b) {
    asm volatile("mma.sync.aligned.m16n8k16.row.col.f32.bf16.bf16.f32 "
                 "{%0,%1,%2,%3}, {%4,%5,%6,%7}, {%8,%9}, {%0,%1,%2,%3};"
                 : "+f"(c[0]), "+f"(c[1]), "+f"(c[2]), "+f"(c[3])
                 : "r"(a[0]), "r"(a[1]), "r"(a[2]), "r"(a[3]), "r"(b[0]), "r"(b[1]));
}

#define CP_ASYNC16(dst, src) \
    asm volatile("cp.async.cg.shared.global [%0], [%1], 16;" :: "r"(dst), "l"(src))
#define CP_COMMIT() asm volatile("cp.async.commit_group;")
#define CP_WAIT0()  asm volatile("cp.async.wait_group 0;" ::: "memory")

// ---------------------------------------------------------------------------
// main: persistent work-stealing, BM=128 x BN=128 tiles (halves rallies,
// B traffic, and prologues per output vs BM=64). 256 thr / 8 warps in a
// 4x2 grid of 32x64 warp tiles (same per-warp shape as the 90.6us kernel),
// 2 CTAs/SM. EARLY skip for dead tiles; one reduction + ticket per CTA.
// ---------------------------------------------------------------------------
__global__ void __launch_bounds__(256, 2)
mi_main_kernel(const float* __restrict__ seq, float* __restrict__ out) {
    extern __shared__ __align__(16) uint8_t dynsm_raw[];
    __shared__ float redp[8], redn[8];
    __shared__ int sh_t;

    const int tid = threadIdx.x;
    const int lane = tid & 31;
    const int w = tid >> 5;        // 0..7
    const int wm = w >> 1;         // warp row (4 x 32 rows)
    const int wn = w & 1;          // warp col (2 x 64 cols)

    const uint32_t rawB = (uint32_t)__cvta_generic_to_shared(dynsm_raw);
    const uint32_t sBase = (rawB + 1023u) & ~1023u;
    uint8_t* dynsm = dynsm_raw + (sBase - rawB);

    float pos = 0.0f, neg = 0.0f;

    while (true) {
        __syncthreads();                       // protect sh_t reuse
        if (tid == 0) sh_t = atomicAdd(&g_fetch, 1);
        __syncthreads();
        const int t = sh_t;
        if (t >= NTILES) break;

        // s-major: alive tiles cluster at low t
        const int s0 = (t >> 7) * 128;
        const int b = t & (Bn - 1);
        const int len = g_lens[b];
        if (s0 >= len) continue;               // dead tile: cheap skip
        const int tok0 = b * Sn + s0;

        float acc[2][8][4];
        #pragma unroll
        for (int i = 0; i < 2; i++)
            #pragma unroll
            for (int j = 0; j < 8; j++)
                #pragma unroll
                for (int r = 0; r < 4; r++) acc[i][j][r] = 0.0f;

        float4 pa[4];   // A half staging: 64 rows x 64 k fp32 / 256 thr

        auto loadA_half = [&](int kb, int h) {
            #pragma unroll
            for (int j = 0; j < 4; j++) {
                int fi = tid + j * 256;            // 1024 float4 per half
                int rw = h * 64 + (fi >> 4);
                int fc = fi & 15;
                pa[j] = *reinterpret_cast<const float4*>(
                    seq + (size_t)(tok0 + rw) * Dn + kb * 64 + fc * 4);
            }
        };
        auto storeA_half = [&](int buf, int h) {
            #pragma unroll
            for (int j = 0; j < 4; j++) {
                int fi = tid + j * 256;
                int rw = h * 64 + (fi >> 4);
                int fc = fi & 15;
                __nv_bfloat162 h0 = __float22bfloat162_rn(make_float2(pa[j].x, pa[j].y));
                __nv_bfloat162 h1 = __float22bfloat162_rn(make_float2(pa[j].z, pa[j].w));
                uint2 vv;
                vv.x = *reinterpret_cast<uint32_t*>(&h0);
                vv.y = *reinterpret_cast<uint32_t*>(&h1);
                uint32_t off = rw * 128 + fc * 8;
                uint32_t sw = off ^ ((off >> 3) & 0x70);
                *reinterpret_cast<uint2*>(dynsm + OFF_A(buf) + sw) = vv;
            }
        };
        auto loadB = [&](int kb, int buf) {
            #pragma unroll
            for (int j = 0; j < 4; j++) {
                int lc = tid + j * 256;            // 1024 16B chunks
                int rw = lc >> 3;
                int cc = lc & 7;
                uint32_t off = rw * 128 + cc * 16;
                uint32_t sw = off ^ ((off >> 3) & 0x70);
                CP_ASYNC16(sBase + OFF_B(buf) + sw,
                           g_ctx_bf16 + rw * Dn + kb * 64 + cc * 8);
            }
        };
        auto compute_ks = [&](int buf, int ks) {
            const uint32_t aB = sBase + OFF_A(buf);
            const uint32_t bB = sBase + OFF_B(buf);
            uint32_t afr[2][4];
            #pragma unroll
            for (int mf = 0; mf < 2; mf++) {
                int r = wm * 32 + mf * 16 + (lane & 15);
                int ch = ks * 2 + (lane >> 4);
                ldm_x4(afr[mf][0], afr[mf][1], afr[mf][2], afr[mf][3],
                       aB + r * 128 + ((ch ^ (r & 7)) << 4));
            }
            uint32_t bfr[8][2];
            #pragma unroll
            for (int nq = 0; nq < 4; nq++) {
                int r = wn * 64 + nq * 16 + (lane & 7) + ((lane & 16) >> 1);
                int ch = ks * 2 + ((lane >> 3) & 1);
                uint32_t t0, t1, t2, t3;
                ldm_x4(t0, t1, t2, t3, bB + r * 128 + ((ch ^ (r & 7)) << 4));
                bfr[nq * 2][0] = t0; bfr[nq * 2][1] = t1;
                bfr[nq * 2 + 1][0] = t2; bfr[nq * 2 + 1][1] = t3;
            }
            #pragma unroll
            for (int mf = 0; mf < 2; mf++)
                #pragma unroll
                for (int nf = 0; nf < 8; nf++)
                    mma_bf16(acc[mf][nf], afr[mf], bfr[nf]);
        };

        // prologue: fill buffer 0
        loadA_half(0, 0); storeA_half(0, 0);
        loadA_half(0, 1); storeA_half(0, 1);
        loadB(0, 0); CP_COMMIT();
        CP_WAIT0();
        __syncthreads();

        for (int kb = 0; kb < 16; kb++) {
            const int cur = kb & 1;
            const int nxt = cur ^ 1;
            if (kb < 15) {
                loadB(kb + 1, nxt);
                CP_COMMIT();
                loadA_half(kb + 1, 0);
            }
            compute_ks(cur, 0);
            compute_ks(cur, 1);
            if (kb < 15) {
                storeA_half(nxt, 0);
                loadA_half(kb + 1, 1);
            }
            compute_ks(cur, 2);
            compute_ks(cur, 3);
            if (kb < 15) {
                storeA_half(nxt, 1);
                CP_WAIT0();
            }
            __syncthreads();
        }

        // JSD epilogue: masked by (s < len), diag/off-diag split
        #pragma unroll
        for (int mf = 0; mf < 2; mf++) {
            #pragma unroll
            for (int nf = 0; nf < 8; nf++) {
                #pragma unroll
                for (int r = 0; r < 4; r++) {
                    int row = wm * 32 + mf * 16 + (lane >> 2) + ((r & 2) ? 8 : 0);
                    int s   = s0 + row;
                    int k   = wn * 64 + nf * 8 + ((lane & 3) << 1) + (r & 1);
                    float v = acc[mf][nf][r];
                    if (s < len) {
                        float sp = fmaxf(-v, 0.0f) + __logf(1.0f + __expf(-fabsf(v)));
                        if (k == b) pos += LOG2F_ - sp;
                        else        neg += sp + v - LOG2F_;
                    }
                }
            }
        }
    }

    // ---- once per CTA: reduction + ticket ----
    #pragma unroll
    for (int off = 16; off > 0; off >>= 1) {
        pos += __shfl_xor_sync(0xffffffffu, pos, off);
        neg += __shfl_xor_sync(0xffffffffu, neg, off);
    }
    if (lane == 0) { redp[w] = pos; redn[w] = neg; }
    __syncthreads();
    if (tid == 0) {
        double p = 0.0, n = 0.0;
        #pragma unroll
        for (int i = 0; i < 8; i++) { p += (double)redp[i]; n += (double)redn[i]; }
        if (p != 0.0 || n != 0.0) {
            atomicAdd(&g_pos_acc, p);
            atomicAdd(&g_neg_acc, n);
        }
        __threadfence();
        int old = atomicAdd(&g_ticket, 1);
        if (old == (int)gridDim.x - 1) {   // last CTA finalizes
            double nn = 0.0;
            for (int i = 0; i < Bn; i++) nn += (double)g_lens[i];
            double pp = atomicAdd(&g_pos_acc, 0.0);
            double qq = atomicAdd(&g_neg_acc, 0.0);
            out[0] = (float)(qq / (nn * (double)(Bn - 1)) - pp / nn);
        }
    }
}

extern "C" void kernel_launch(void* const* d_in, const int* in_sizes, int n_in,
                              void* d_out, int out_size) {
    const float* seq  = (const float*)d_in[0];
    const float* ctx  = (const float*)d_in[1];
    const int*   mask = (const int*)d_in[2];
    static bool attr_set = false;
    if (!attr_set) {
        cudaFuncSetAttribute(mi_main_kernel,
                             cudaFuncAttributeMaxDynamicSharedMemorySize, SMEM_BYTES);
        attr_set = true;
    }
    prep_kernel<<<Bn, 256>>>(ctx, mask);
    mi_main_kernel<<<NCTA, 256, SMEM_BYTES>>>(seq, (float*)d_out);
}